// round 1
// baseline (speedup 1.0000x reference)
#include <cuda_runtime.h>
#include <math.h>

// ---------------- scratch (static device globals; no allocation) ----------------
__device__ float g_q[16 * 4096];
__device__ float g_s[16 * 4096];
__device__ float g_y[16 * 256];
__device__ float g_ctx[16 * 256];

// ---------------------------------------------------------------------------
// Kernel 1: V = W_v(256x256) @ x[b](256x4096), write relu(V) into out.
// Blocks with blockIdx.y==0 additionally accumulate q[n] = w_q . x[:,n]
// using the Bs tiles already staged in shared memory (q costs ~0 extra HBM).
// Classic 128x128x8 SGEMM, 256 threads, 8x8 register micro-tiles.
// ---------------------------------------------------------------------------
__global__ __launch_bounds__(256, 2) void gemm_vq(const float* __restrict__ x,
                                                  const float* __restrict__ W,
                                                  float* __restrict__ out)
{
    const int b     = blockIdx.z;
    const int nBase = blockIdx.x * 128;
    const int mBase = blockIdx.y * 128;
    const float* Bp = x + (size_t)b * 256 * 4096;

    __shared__ float As[8][128];
    __shared__ float Bs[8][128];
    __shared__ float wqs[8];

    const int tid  = threadIdx.x;
    const int arow = tid >> 1;          // 0..127
    const int acol = (tid & 1) << 2;    // 0 or 4
    const int brow = tid >> 5;          // 0..7
    const int bcol = (tid & 31) << 2;   // 0..124
    const int tx   = tid & 15;
    const int ty   = tid >> 4;

    float acc[8][8];
#pragma unroll
    for (int i = 0; i < 8; i++)
#pragma unroll
        for (int j = 0; j < 8; j++) acc[i][j] = 0.f;
    float qacc = 0.f;

    const float* Arow = W + (size_t)(257 + mBase + arow) * 256 + acol;

    for (int k0 = 0; k0 < 256; k0 += 8) {
        float4 av = *(const float4*)(Arow + k0);
        float4 bv = *(const float4*)(Bp + (size_t)(k0 + brow) * 4096 + nBase + bcol);
        As[acol + 0][arow] = av.x;
        As[acol + 1][arow] = av.y;
        As[acol + 2][arow] = av.z;
        As[acol + 3][arow] = av.w;
        *(float4*)&Bs[brow][bcol] = bv;
        if (blockIdx.y == 0 && tid < 8) wqs[tid] = W[k0 + tid];  // W row 0 = w_q
        __syncthreads();

#pragma unroll
        for (int k = 0; k < 8; k++) {
            float4 a0 = *(const float4*)&As[k][ty * 4];
            float4 a1 = *(const float4*)&As[k][64 + ty * 4];
            float4 b0 = *(const float4*)&Bs[k][tx * 4];
            float4 b1 = *(const float4*)&Bs[k][64 + tx * 4];
            float ar[8] = {a0.x, a0.y, a0.z, a0.w, a1.x, a1.y, a1.z, a1.w};
            float br[8] = {b0.x, b0.y, b0.z, b0.w, b1.x, b1.y, b1.z, b1.w};
#pragma unroll
            for (int i = 0; i < 8; i++)
#pragma unroll
                for (int j = 0; j < 8; j++) acc[i][j] += ar[i] * br[j];
        }
        if (blockIdx.y == 0 && tid < 128) {
#pragma unroll
            for (int k = 0; k < 8; k++) qacc += wqs[k] * Bs[k][tid];
        }
        __syncthreads();
    }

    // write relu(V)
#pragma unroll
    for (int i = 0; i < 8; i++) {
        int r = mBase + ((i < 4) ? (ty * 4 + i) : (64 + ty * 4 + (i - 4)));
        float* orow = out + ((size_t)b * 256 + r) * 4096 + nBase;
        float4 v0 = make_float4(fmaxf(acc[i][0], 0.f), fmaxf(acc[i][1], 0.f),
                                fmaxf(acc[i][2], 0.f), fmaxf(acc[i][3], 0.f));
        float4 v1 = make_float4(fmaxf(acc[i][4], 0.f), fmaxf(acc[i][5], 0.f),
                                fmaxf(acc[i][6], 0.f), fmaxf(acc[i][7], 0.f));
        *(float4*)(orow + tx * 4)      = v0;
        *(float4*)(orow + 64 + tx * 4) = v1;
    }
    if (blockIdx.y == 0 && tid < 128) g_q[b * 4096 + nBase + tid] = qacc;
}

// ---------------------------------------------------------------------------
// Kernel 2: scores = softmax(q) over n=4096 per batch. 16 blocks x 512 thr.
// ---------------------------------------------------------------------------
__global__ __launch_bounds__(512) void softmax_k()
{
    const int b = blockIdx.x;
    const float4* q4 = (const float4*)(g_q + b * 4096);
    float4* s4 = (float4*)(g_s + b * 4096);

    float4 v0 = q4[threadIdx.x];
    float4 v1 = q4[threadIdx.x + 512];

    float m = fmaxf(fmaxf(fmaxf(v0.x, v0.y), fmaxf(v0.z, v0.w)),
                    fmaxf(fmaxf(v1.x, v1.y), fmaxf(v1.z, v1.w)));

    __shared__ float redm[16];
    __shared__ float reds[16];
#pragma unroll
    for (int o = 16; o > 0; o >>= 1) m = fmaxf(m, __shfl_xor_sync(0xffffffffu, m, o));
    if ((threadIdx.x & 31) == 0) redm[threadIdx.x >> 5] = m;
    __syncthreads();
    float gm = redm[0];
#pragma unroll
    for (int i = 1; i < 16; i++) gm = fmaxf(gm, redm[i]);

    v0.x = __expf(v0.x - gm); v0.y = __expf(v0.y - gm);
    v0.z = __expf(v0.z - gm); v0.w = __expf(v0.w - gm);
    v1.x = __expf(v1.x - gm); v1.y = __expf(v1.y - gm);
    v1.z = __expf(v1.z - gm); v1.w = __expf(v1.w - gm);

    float sum = v0.x + v0.y + v0.z + v0.w + v1.x + v1.y + v1.z + v1.w;
#pragma unroll
    for (int o = 16; o > 0; o >>= 1) sum += __shfl_xor_sync(0xffffffffu, sum, o);
    if ((threadIdx.x & 31) == 0) reds[threadIdx.x >> 5] = sum;
    __syncthreads();
    float tot = 0.f;
#pragma unroll
    for (int i = 0; i < 16; i++) tot += reds[i];
    float inv = 1.f / tot;

    v0.x *= inv; v0.y *= inv; v0.z *= inv; v0.w *= inv;
    v1.x *= inv; v1.y *= inv; v1.z *= inv; v1.w *= inv;
    s4[threadIdx.x]       = v0;
    s4[threadIdx.x + 512] = v1;
}

// ---------------------------------------------------------------------------
// Kernel 3: y[b,c] = sum_n x[b,c,n] * s[b,n].  Grid (256, 16), 256 threads.
// ---------------------------------------------------------------------------
__global__ __launch_bounds__(256) void y_kernel(const float* __restrict__ x)
{
    const int c = blockIdx.x, b = blockIdx.y;
    const float4* xr = (const float4*)(x + ((size_t)b * 256 + c) * 4096);
    const float4* sr = (const float4*)(g_s + b * 4096);
    float acc = 0.f;
    for (int i = threadIdx.x; i < 1024; i += 256) {
        float4 a = xr[i];
        float4 s = sr[i];
        acc += a.x * s.x + a.y * s.y + a.z * s.z + a.w * s.w;
    }
#pragma unroll
    for (int o = 16; o > 0; o >>= 1) acc += __shfl_xor_sync(0xffffffffu, acc, o);
    __shared__ float red[8];
    if ((threadIdx.x & 31) == 0) red[threadIdx.x >> 5] = acc;
    __syncthreads();
    if (threadIdx.x == 0) {
        float t = 0.f;
#pragma unroll
        for (int i = 0; i < 8; i++) t += red[i];
        g_y[b * 256 + c] = t;
    }
}

// ---------------------------------------------------------------------------
// Kernel 4: ctx[b,d] = sum_c W[1+d,c] * y[b,c].  16 blocks x 256 threads.
// ---------------------------------------------------------------------------
__global__ __launch_bounds__(256) void ctx_kernel(const float* __restrict__ W)
{
    const int b = blockIdx.x;
    __shared__ float ys[256];
    ys[threadIdx.x] = g_y[b * 256 + threadIdx.x];
    __syncthreads();
    const float* wr = W + (size_t)(1 + threadIdx.x) * 256;
    float acc = 0.f;
#pragma unroll 8
    for (int c = 0; c < 256; c++) acc += wr[c] * ys[c];
    g_ctx[b * 256 + threadIdx.x] = acc;
}

// ---------------------------------------------------------------------------
// Kernel 5: out[b,d,n] *= ctx[b,d]   (out already holds relu(V)).
// 4M float4s. row = i >> 10 (1024 float4 per (b,d) row).
// ---------------------------------------------------------------------------
__global__ __launch_bounds__(256) void scale_kernel(float* __restrict__ out)
{
    int i = blockIdx.x * 256 + threadIdx.x;
    float4* o4 = (float4*)out;
    float c = g_ctx[i >> 10];
    float4 v = o4[i];
    v.x *= c; v.y *= c; v.z *= c; v.w *= c;
    o4[i] = v;
}

// ---------------------------------------------------------------------------
extern "C" void kernel_launch(void* const* d_in, const int* in_sizes, int n_in,
                              void* d_out, int out_size)
{
    const float* x = (const float*)d_in[0];   // (16, 256, 64, 64) f32
    const float* W = (const float*)d_in[1];   // (513, 256) f32
    float* out = (float*)d_out;               // (16, 256, 64, 64) f32

    dim3 g1(4096 / 128, 256 / 128, 16);       // (32, 2, 16)
    gemm_vq<<<g1, 256>>>(x, W, out);
    softmax_k<<<16, 512>>>();
    y_kernel<<<dim3(256, 16), 256>>>(x);
    ctx_kernel<<<16, 256>>>(W);
    scale_kernel<<<(16 * 256 * 4096 / 4) / 256, 256>>>(out);
}

// round 3
// speedup vs baseline: 1.9407x; 1.9407x over previous
#include <cuda_runtime.h>
#include <cuda_bf16.h>
#include <cstdint>
#include <math.h>

// ---------------- scratch (static device globals; no allocation) ----------------
__device__ float g_q[16 * 4096];
__device__ float g_s[16 * 4096];
__device__ float g_y[16 * 256];
__device__ float g_ctx[16 * 256];
// x split into bf16 hi/lo, SAME layout as x: [b][c][n]
__device__ __nv_bfloat16 g_xh[(size_t)16 * 256 * 4096];
__device__ __nv_bfloat16 g_xl[(size_t)16 * 256 * 4096];
// W_v rows (257..512) split into bf16 hi/lo, row-major [256 m][256 k]
__device__ __nv_bfloat16 g_wh[256 * 256];
__device__ __nv_bfloat16 g_wl[256 * 256];

__device__ __forceinline__ uint32_t smem_u32(const void* p) {
    uint32_t a;
    asm("{ .reg .u64 t; cvta.to.shared.u64 t, %1; cvt.u32.u64 %0, t; }" : "=r"(a) : "l"(p));
    return a;
}

#define LDSM_X4(r, addr) \
    asm volatile("ldmatrix.sync.aligned.m8n8.x4.shared.b16 {%0,%1,%2,%3}, [%4];" \
        : "=r"((r)[0]), "=r"((r)[1]), "=r"((r)[2]), "=r"((r)[3]) : "r"(addr))
#define LDSM_X4T(r, addr) \
    asm volatile("ldmatrix.sync.aligned.m8n8.x4.trans.shared.b16 {%0,%1,%2,%3}, [%4];" \
        : "=r"((r)[0]), "=r"((r)[1]), "=r"((r)[2]), "=r"((r)[3]) : "r"(addr))
#define MMA_BF16(d, a, b0, b1) \
    asm volatile("mma.sync.aligned.m16n8k16.row.col.f32.bf16.bf16.f32 " \
        "{%0,%1,%2,%3}, {%4,%5,%6,%7}, {%8,%9}, {%0,%1,%2,%3};" \
        : "+f"((d)[0]), "+f"((d)[1]), "+f"((d)[2]), "+f"((d)[3]) \
        : "r"((a)[0]), "r"((a)[1]), "r"((a)[2]), "r"((a)[3]), "r"(b0), "r"(b1))

// ---------------------------------------------------------------------------
// Kernel A: split W_v (rows 257..512) into bf16 hi/lo.
// ---------------------------------------------------------------------------
__global__ __launch_bounds__(256) void conv_w(const float* __restrict__ W)
{
    int r = blockIdx.x, c = threadIdx.x;
    float v = W[(size_t)(257 + r) * 256 + c];
    __nv_bfloat16 h = __float2bfloat16(v);
    g_wh[r * 256 + c] = h;
    g_wl[r * 256 + c] = __float2bfloat16(v - __bfloat162float(h));
}

// ---------------------------------------------------------------------------
// Kernel B: split x -> hi/lo bf16 (same layout), and q[b,n] = sum_c W[0,c]*x
// in the same pass (each block owns the full c range for its n-slice).
// Grid (32 n-tiles, 16 b), 256 threads: 2 threads per n (c parity split).
// ---------------------------------------------------------------------------
__global__ __launch_bounds__(256) void conv_xq(const float* __restrict__ x,
                                               const float* __restrict__ W)
{
    __shared__ float s_wq[256];
    __shared__ float s_red[256];
    const int b = blockIdx.y;
    const int nBase = blockIdx.x * 128;
    const int t = threadIdx.x;
    const int half = t >> 7;      // c parity
    const int n = t & 127;

    s_wq[t] = W[t];               // W row 0 = q weights
    __syncthreads();

    float qp = 0.f;
#pragma unroll 8
    for (int c = half; c < 256; c += 2) {
        size_t idx = ((size_t)b * 256 + c) * 4096 + nBase + n;
        float v = x[idx];
        __nv_bfloat16 h = __float2bfloat16(v);
        g_xh[idx] = h;
        g_xl[idx] = __float2bfloat16(v - __bfloat162float(h));
        qp += s_wq[c] * v;
    }
    s_red[t] = qp;
    __syncthreads();
    if (t < 128) g_q[b * 4096 + nBase + t] = s_red[t] + s_red[t + 128];
}

// ---------------------------------------------------------------------------
// Kernel C: softmax over q (16 x 4096).
// ---------------------------------------------------------------------------
__global__ __launch_bounds__(512) void softmax_k()
{
    const int b = blockIdx.x;
    const float4* q4 = (const float4*)(g_q + b * 4096);
    float4* s4 = (float4*)(g_s + b * 4096);

    float4 v0 = q4[threadIdx.x];
    float4 v1 = q4[threadIdx.x + 512];

    float m = fmaxf(fmaxf(fmaxf(v0.x, v0.y), fmaxf(v0.z, v0.w)),
                    fmaxf(fmaxf(v1.x, v1.y), fmaxf(v1.z, v1.w)));
    __shared__ float redm[16];
    __shared__ float reds[16];
#pragma unroll
    for (int o = 16; o > 0; o >>= 1) m = fmaxf(m, __shfl_xor_sync(0xffffffffu, m, o));
    if ((threadIdx.x & 31) == 0) redm[threadIdx.x >> 5] = m;
    __syncthreads();
    float gm = redm[0];
#pragma unroll
    for (int i = 1; i < 16; i++) gm = fmaxf(gm, redm[i]);

    v0.x = __expf(v0.x - gm); v0.y = __expf(v0.y - gm);
    v0.z = __expf(v0.z - gm); v0.w = __expf(v0.w - gm);
    v1.x = __expf(v1.x - gm); v1.y = __expf(v1.y - gm);
    v1.z = __expf(v1.z - gm); v1.w = __expf(v1.w - gm);

    float sum = v0.x + v0.y + v0.z + v0.w + v1.x + v1.y + v1.z + v1.w;
#pragma unroll
    for (int o = 16; o > 0; o >>= 1) sum += __shfl_xor_sync(0xffffffffu, sum, o);
    if ((threadIdx.x & 31) == 0) reds[threadIdx.x >> 5] = sum;
    __syncthreads();
    float tot = 0.f;
#pragma unroll
    for (int i = 0; i < 16; i++) tot += reds[i];
    float inv = 1.f / tot;

    v0.x *= inv; v0.y *= inv; v0.z *= inv; v0.w *= inv;
    v1.x *= inv; v1.y *= inv; v1.z *= inv; v1.w *= inv;
    s4[threadIdx.x] = v0;
    s4[threadIdx.x + 512] = v1;
}

// ---------------------------------------------------------------------------
// Kernel D: y[b,c] = sum_n x[b,c,n] * s[b,n].
// ---------------------------------------------------------------------------
__global__ __launch_bounds__(256) void y_kernel(const float* __restrict__ x)
{
    const int c = blockIdx.x, b = blockIdx.y;
    const float4* xr = (const float4*)(x + ((size_t)b * 256 + c) * 4096);
    const float4* sr = (const float4*)(g_s + b * 4096);
    float acc = 0.f;
    for (int i = threadIdx.x; i < 1024; i += 256) {
        float4 a = xr[i];
        float4 s = sr[i];
        acc += a.x * s.x + a.y * s.y + a.z * s.z + a.w * s.w;
    }
#pragma unroll
    for (int o = 16; o > 0; o >>= 1) acc += __shfl_xor_sync(0xffffffffu, acc, o);
    __shared__ float red[8];
    if ((threadIdx.x & 31) == 0) red[threadIdx.x >> 5] = acc;
    __syncthreads();
    if (threadIdx.x == 0) {
        float tsum = 0.f;
#pragma unroll
        for (int i = 0; i < 8; i++) tsum += red[i];
        g_y[b * 256 + c] = tsum;
    }
}

// ---------------------------------------------------------------------------
// Kernel E: ctx[b,d] = sum_c W[1+d,c] * y[b,c]. One warp per d, coalesced.
// ---------------------------------------------------------------------------
__global__ __launch_bounds__(256) void ctx_kernel(const float* __restrict__ W)
{
    const int b = blockIdx.x;
    const int w = threadIdx.x >> 5, l = threadIdx.x & 31;
    const int d = blockIdx.y * 8 + w;
    __shared__ float ys[256];
    ys[threadIdx.x] = g_y[b * 256 + threadIdx.x];
    __syncthreads();
    const float* wr = W + (size_t)(1 + d) * 256;
    float acc = 0.f;
#pragma unroll
    for (int c = l; c < 256; c += 32) acc += wr[c] * ys[c];
#pragma unroll
    for (int o = 16; o > 0; o >>= 1) acc += __shfl_xor_sync(0xffffffffu, acc, o);
    if (l == 0) g_ctx[b * 256 + d] = acc;
}

// ---------------------------------------------------------------------------
// Kernel F: mma.sync bf16 GEMM  V = Wv @ x  (M=256 x N=65536 x K=256):
//   D = Ah*Bh + Ah*Bl + Al*Bh  (fp32 accumulators; AlBl dropped, ~2^-18)
// CTA tile 128(m) x 128(n), K-chunks of 64 staged in smem.
// 8 warps, warp tile 64(m) x 32(n). A: ldmatrix.x4; B: ldmatrix.x4.trans
// (x stays [c][n] — no transpose pass needed).
// Epilogue fuses out = relu(V) * ctx[b,m], 32B-aligned float2 stores.
// smem (dynamic 64KB): Ah@0 Al@16K (128 rows x 128B, sw128 xor)
//                      Bh@32K Bl@48K (64 rows x 256B, row%8 xor)
// ---------------------------------------------------------------------------
__global__ __launch_bounds__(256, 1) void gemm_tc(float* __restrict__ out)
{
    extern __shared__ char sm[];
    __shared__ float s_ctx[128];

    const int nBase = blockIdx.x * 128;
    const int mBase = blockIdx.y * 128;
    const int b = blockIdx.z;
    const uint32_t smb = smem_u32(sm);

    const int t = threadIdx.x;
    const int w = t >> 5, L = t & 31;
    const int mw = w & 1, nw = w >> 1;      // warp tile: m (mw*64), n (nw*32)

    if (t < 128) s_ctx[t] = g_ctx[b * 256 + mBase + t];

    float acc[4][4][4];
#pragma unroll
    for (int i = 0; i < 4; i++)
#pragma unroll
        for (int j = 0; j < 4; j++)
#pragma unroll
            for (int k = 0; k < 4; k++) acc[i][j][k] = 0.f;

    const int rowL = L & 15;     // ldmatrix lane row within 16
    const int selL = L >> 4;     // ldmatrix lane half-select

    for (int ch = 0; ch < 4; ch++) {
        const int k0 = ch * 64;
        // ---- stage Ah/Al (128x64) and Bh/Bl (64x128) ----
#pragma unroll
        for (int i = 0; i < 4; i++) {
            int u = i * 256 + t;
            // A: 128 rows x 8 c16
            int ra = u >> 3, ca = u & 7;
            uint32_t offA = (uint32_t)(ra * 128 + ca * 16);
            uint32_t swA = offA ^ ((offA >> 3) & 0x70);
            size_t gA = (size_t)(mBase + ra) * 256 + k0 + ca * 8;
            *(uint4*)(sm + swA)         = *(const uint4*)(g_wh + gA);
            *(uint4*)(sm + 16384 + swA) = *(const uint4*)(g_wl + gA);
            // B: 64 rows x 16 c16
            int rb = u >> 4, cb = u & 15;
            uint32_t offB = (uint32_t)(rb * 256 + cb * 16);
            uint32_t swB = offB ^ (((offB >> 8) & 7) << 4);
            size_t gB = ((size_t)b * 256 + k0 + rb) * 4096 + nBase + cb * 8;
            *(uint4*)(sm + 32768 + swB) = *(const uint4*)(g_xh + gB);
            *(uint4*)(sm + 49152 + swB) = *(const uint4*)(g_xl + gB);
        }
        __syncthreads();

#pragma unroll
        for (int ks = 0; ks < 4; ks++) {
            uint32_t Ah[4][4], Al[4][4], Bh[2][4], Bl[2][4];
#pragma unroll
            for (int mf = 0; mf < 4; mf++) {
                uint32_t offA = (uint32_t)((mw * 64 + mf * 16 + rowL) * 128 +
                                           (ks * 2 + selL) * 16);
                uint32_t a = smb + (offA ^ ((offA >> 3) & 0x70));
                LDSM_X4(Ah[mf], a);
                LDSM_X4(Al[mf], a + 16384);
            }
#pragma unroll
            for (int ng = 0; ng < 2; ng++) {
                uint32_t offB = (uint32_t)((ks * 16 + rowL) * 256 +
                                           (nw * 4 + ng * 2 + selL) * 16);
                uint32_t aB = smb + 32768 + (offB ^ (((offB >> 8) & 7) << 4));
                LDSM_X4T(Bh[ng], aB);
                LDSM_X4T(Bl[ng], aB + 16384);
            }
#pragma unroll
            for (int mf = 0; mf < 4; mf++)
#pragma unroll
                for (int nf = 0; nf < 4; nf++) {
                    const int ng = nf >> 1, p = (nf & 1) * 2;
                    MMA_BF16(acc[mf][nf], Ah[mf], Bh[ng][p], Bh[ng][p + 1]);
                    MMA_BF16(acc[mf][nf], Ah[mf], Bl[ng][p], Bl[ng][p + 1]);
                    MMA_BF16(acc[mf][nf], Al[mf], Bh[ng][p], Bh[ng][p + 1]);
                }
        }
        __syncthreads();
    }

    // ---- epilogue: out = relu(V) * ctx ----
    const int gid = L >> 2, tig = L & 3;
#pragma unroll
    for (int mf = 0; mf < 4; mf++) {
        const int r0 = mw * 64 + mf * 16 + gid;
        const float c0 = s_ctx[r0], c1 = s_ctx[r0 + 8];
        float* o0 = out + ((size_t)b * 256 + mBase + r0) * 4096 + nBase;
        float* o1 = o0 + (size_t)8 * 4096;
#pragma unroll
        for (int nf = 0; nf < 4; nf++) {
            const int col = nw * 32 + nf * 8 + tig * 2;
            float2 v0 = make_float2(fmaxf(acc[mf][nf][0], 0.f) * c0,
                                    fmaxf(acc[mf][nf][1], 0.f) * c0);
            float2 v1 = make_float2(fmaxf(acc[mf][nf][2], 0.f) * c1,
                                    fmaxf(acc[mf][nf][3], 0.f) * c1);
            *(float2*)(o0 + col) = v0;
            *(float2*)(o1 + col) = v1;
        }
    }
}

// ---------------------------------------------------------------------------
extern "C" void kernel_launch(void* const* d_in, const int* in_sizes, int n_in,
                              void* d_out, int out_size)
{
    const float* x = (const float*)d_in[0];  // (16, 256, 64, 64) f32
    const float* W = (const float*)d_in[1];  // (513, 256) f32
    float* out = (float*)d_out;              // (16, 256, 64, 64) f32

    cudaFuncSetAttribute(gemm_tc, cudaFuncAttributeMaxDynamicSharedMemorySize, 65536);

    conv_w<<<256, 256>>>(W);
    conv_xq<<<dim3(32, 16), 256>>>(x, W);
    softmax_k<<<16, 512>>>();
    y_kernel<<<dim3(256, 16), 256>>>(x);
    ctx_kernel<<<dim3(16, 32), 256>>>(W);
    gemm_tc<<<dim3(32, 2, 16), 256, 65536>>>(out);
}

// round 4
// speedup vs baseline: 2.0197x; 1.0407x over previous
#include <cuda_runtime.h>
#include <cuda_fp16.h>
#include <cstdint>
#include <math.h>

// ---------------- scratch (static device globals; no allocation) ----------------
__device__ float g_q[16 * 4096];
__device__ float g_s[16 * 4096];
__device__ float g_y[16 * 256];
__device__ float g_ctx[16 * 256];
// x as single fp16, SAME layout as x: [b][c][n]
__device__ __half g_xh[(size_t)16 * 256 * 4096];
// W_v rows (257..512) split into fp16 hi/lo, row-major [256 m][256 k]
__device__ __half g_wh[256 * 256];
__device__ __half g_wl[256 * 256];

__device__ __forceinline__ uint32_t smem_u32(const void* p) {
    uint32_t a;
    asm("{ .reg .u64 t; cvta.to.shared.u64 t, %1; cvt.u32.u64 %0, t; }" : "=r"(a) : "l"(p));
    return a;
}

#define LDSM_X4(r, addr) \
    asm volatile("ldmatrix.sync.aligned.m8n8.x4.shared.b16 {%0,%1,%2,%3}, [%4];" \
        : "=r"((r)[0]), "=r"((r)[1]), "=r"((r)[2]), "=r"((r)[3]) : "r"(addr))
#define LDSM_X4T(r, addr) \
    asm volatile("ldmatrix.sync.aligned.m8n8.x4.trans.shared.b16 {%0,%1,%2,%3}, [%4];" \
        : "=r"((r)[0]), "=r"((r)[1]), "=r"((r)[2]), "=r"((r)[3]) : "r"(addr))
#define MMA_F16(d, a, b0, b1) \
    asm volatile("mma.sync.aligned.m16n8k16.row.col.f32.f16.f16.f32 " \
        "{%0,%1,%2,%3}, {%4,%5,%6,%7}, {%8,%9}, {%0,%1,%2,%3};" \
        : "+f"((d)[0]), "+f"((d)[1]), "+f"((d)[2]), "+f"((d)[3]) \
        : "r"((a)[0]), "r"((a)[1]), "r"((a)[2]), "r"((a)[3]), "r"(b0), "r"(b1))
#define CP_ASYNC16(dst, src) \
    asm volatile("cp.async.cg.shared.global [%0], [%1], 16;" :: "r"(dst), "l"(src))
#define CP_COMMIT() asm volatile("cp.async.commit_group;" ::: "memory")
#define CP_WAIT(n)  asm volatile("cp.async.wait_group %0;" :: "n"(n) : "memory")

// ---------------------------------------------------------------------------
// Kernel A: split W_v (rows 257..512) into fp16 hi/lo.
// ---------------------------------------------------------------------------
__global__ __launch_bounds__(256) void conv_w(const float* __restrict__ W)
{
    int r = blockIdx.x, c = threadIdx.x;
    float v = W[(size_t)(257 + r) * 256 + c];
    __half h = __float2half_rn(v);
    g_wh[r * 256 + c] = h;
    g_wl[r * 256 + c] = __float2half_rn(v - __half2float(h));
}

// ---------------------------------------------------------------------------
// Kernel B: x -> fp16 (same layout) and q[b,n] = sum_c W[0,c]*x[b,c,n].
// Grid (32 n-tiles, 16 b), 256 threads: 2 threads per n (c parity split).
// ---------------------------------------------------------------------------
__global__ __launch_bounds__(256) void conv_xq(const float* __restrict__ x,
                                               const float* __restrict__ W)
{
    __shared__ float s_wq[256];
    __shared__ float s_red[256];
    const int b = blockIdx.y;
    const int nBase = blockIdx.x * 128;
    const int t = threadIdx.x;
    const int half = t >> 7;
    const int n = t & 127;

    s_wq[t] = W[t];  // W row 0 = q weights
    __syncthreads();

    float qp = 0.f;
#pragma unroll 8
    for (int c = half; c < 256; c += 2) {
        size_t idx = ((size_t)b * 256 + c) * 4096 + nBase + n;
        float v = x[idx];
        g_xh[idx] = __float2half_rn(v);
        qp += s_wq[c] * v;
    }
    s_red[t] = qp;
    __syncthreads();
    if (t < 128) g_q[b * 4096 + nBase + t] = s_red[t] + s_red[t + 128];
}

// ---------------------------------------------------------------------------
// Kernel C: softmax over q (16 x 4096).
// ---------------------------------------------------------------------------
__global__ __launch_bounds__(512) void softmax_k()
{
    const int b = blockIdx.x;
    const float4* q4 = (const float4*)(g_q + b * 4096);
    float4* s4 = (float4*)(g_s + b * 4096);

    float4 v0 = q4[threadIdx.x];
    float4 v1 = q4[threadIdx.x + 512];

    float m = fmaxf(fmaxf(fmaxf(v0.x, v0.y), fmaxf(v0.z, v0.w)),
                    fmaxf(fmaxf(v1.x, v1.y), fmaxf(v1.z, v1.w)));
    __shared__ float redm[16];
    __shared__ float reds[16];
#pragma unroll
    for (int o = 16; o > 0; o >>= 1) m = fmaxf(m, __shfl_xor_sync(0xffffffffu, m, o));
    if ((threadIdx.x & 31) == 0) redm[threadIdx.x >> 5] = m;
    __syncthreads();
    float gm = redm[0];
#pragma unroll
    for (int i = 1; i < 16; i++) gm = fmaxf(gm, redm[i]);

    v0.x = __expf(v0.x - gm); v0.y = __expf(v0.y - gm);
    v0.z = __expf(v0.z - gm); v0.w = __expf(v0.w - gm);
    v1.x = __expf(v1.x - gm); v1.y = __expf(v1.y - gm);
    v1.z = __expf(v1.z - gm); v1.w = __expf(v1.w - gm);

    float sum = v0.x + v0.y + v0.z + v0.w + v1.x + v1.y + v1.z + v1.w;
#pragma unroll
    for (int o = 16; o > 0; o >>= 1) sum += __shfl_xor_sync(0xffffffffu, sum, o);
    if ((threadIdx.x & 31) == 0) reds[threadIdx.x >> 5] = sum;
    __syncthreads();
    float tot = 0.f;
#pragma unroll
    for (int i = 0; i < 16; i++) tot += reds[i];
    float inv = 1.f / tot;

    v0.x *= inv; v0.y *= inv; v0.z *= inv; v0.w *= inv;
    v1.x *= inv; v1.y *= inv; v1.z *= inv; v1.w *= inv;
    s4[threadIdx.x] = v0;
    s4[threadIdx.x + 512] = v1;
}

// ---------------------------------------------------------------------------
// Kernel D: y[b,c] = sum_n x[b,c,n] * s[b,n].  (reads fp32 x: keeps epilogue
// error contribution ~0; x is L2-warm after conv_xq)
// ---------------------------------------------------------------------------
__global__ __launch_bounds__(256) void y_kernel(const float* __restrict__ x)
{
    const int c = blockIdx.x, b = blockIdx.y;
    const float4* xr = (const float4*)(x + ((size_t)b * 256 + c) * 4096);
    const float4* sr = (const float4*)(g_s + b * 4096);
    float acc = 0.f;
    for (int i = threadIdx.x; i < 1024; i += 256) {
        float4 a = xr[i];
        float4 s = sr[i];
        acc += a.x * s.x + a.y * s.y + a.z * s.z + a.w * s.w;
    }
#pragma unroll
    for (int o = 16; o > 0; o >>= 1) acc += __shfl_xor_sync(0xffffffffu, acc, o);
    __shared__ float red[8];
    if ((threadIdx.x & 31) == 0) red[threadIdx.x >> 5] = acc;
    __syncthreads();
    if (threadIdx.x == 0) {
        float tsum = 0.f;
#pragma unroll
        for (int i = 0; i < 8; i++) tsum += red[i];
        g_y[b * 256 + c] = tsum;
    }
}

// ---------------------------------------------------------------------------
// Kernel E: ctx[b,d] = sum_c W[1+d,c] * y[b,c]. One warp per d, coalesced.
// ---------------------------------------------------------------------------
__global__ __launch_bounds__(256) void ctx_kernel(const float* __restrict__ W)
{
    const int b = blockIdx.x;
    const int w = threadIdx.x >> 5, l = threadIdx.x & 31;
    const int d = blockIdx.y * 8 + w;
    __shared__ float ys[256];
    ys[threadIdx.x] = g_y[b * 256 + threadIdx.x];
    __syncthreads();
    const float* wr = W + (size_t)(1 + d) * 256;
    float acc = 0.f;
#pragma unroll
    for (int c = l; c < 256; c += 32) acc += wr[c] * ys[c];
#pragma unroll
    for (int o = 16; o > 0; o >>= 1) acc += __shfl_xor_sync(0xffffffffu, acc, o);
    if (l == 0) g_ctx[b * 256 + d] = acc;
}

// ---------------------------------------------------------------------------
// Kernel F: mma.sync fp16 GEMM  V = Wv @ x  (M=256 x N=65536 x K=256):
//   D = Ah*B + Al*B  (fp32 acc; W split fp16 hi/lo, x single fp16)
// CTA tile 128(m) x 128(n), K-chunks of 64, cp.async 2-stage pipeline.
// 8 warps, warp tile 64(m) x 32(n). Epilogue fuses out = relu(V)*ctx.
// smem/stage (48KB): Ah@0 Al@16K (128r x 128B, sw128 xor)
//                    B @32K      (64r x 256B, row%8 xor)
// ---------------------------------------------------------------------------
#define STAGE_BYTES 49152

__global__ __launch_bounds__(256, 1) void gemm_tc(float* __restrict__ out)
{
    extern __shared__ char sm[];
    __shared__ float s_ctx[128];

    const int nBase = blockIdx.x * 128;
    const int mBase = blockIdx.y * 128;
    const int b = blockIdx.z;
    const uint32_t smb = smem_u32(sm);

    const int t = threadIdx.x;
    const int w = t >> 5, L = t & 31;
    const int mw = w & 1, nw = w >> 1;

    if (t < 128) s_ctx[t] = g_ctx[b * 256 + mBase + t];

    // per-thread staging indices (4 x 16B per tile class)
    const int ra = t >> 1, ca = t & 1;            // A: 128 rows x 2 c32 (x4 c16 pairs)
    const int rb = t >> 2, cb = t & 3;            // B: 64 rows x 4 c64

    auto stage = [&](int ch, int buf) {
        const int k0 = ch * 64;
        const uint32_t base = smb + buf * STAGE_BYTES;
#pragma unroll
        for (int i = 0; i < 4; i++) {
            // A: row ra, 16B chunk (ca*4 + i)
            int c16 = ca * 4 + i;
            uint32_t offA = (uint32_t)(ra * 128 + c16 * 16);
            uint32_t swA = offA ^ ((offA >> 3) & 0x70);
            size_t gA = (size_t)(mBase + ra) * 256 + k0 + c16 * 8;
            CP_ASYNC16(base + swA,         g_wh + gA);
            CP_ASYNC16(base + 16384 + swA, g_wl + gA);
            // B: row rb, 16B chunk (cb*4 + i)
            int c16b = cb * 4 + i;
            uint32_t offB = (uint32_t)(rb * 256 + c16b * 16);
            uint32_t swB = offB ^ (((offB >> 8) & 7) << 4);
            size_t gB = ((size_t)b * 256 + k0 + rb) * 4096 + nBase + c16b * 8;
            CP_ASYNC16(base + 32768 + swB, g_xh + gB);
        }
    };

    float acc[4][4][4];
#pragma unroll
    for (int i = 0; i < 4; i++)
#pragma unroll
        for (int j = 0; j < 4; j++)
#pragma unroll
            for (int k = 0; k < 4; k++) acc[i][j][k] = 0.f;

    const int rowL = L & 15;
    const int selL = L >> 4;

    stage(0, 0);
    CP_COMMIT();

    for (int ch = 0; ch < 4; ch++) {
        if (ch < 3) {
            stage(ch + 1, (ch + 1) & 1);
            CP_COMMIT();
            CP_WAIT(1);
        } else {
            CP_WAIT(0);
        }
        __syncthreads();
        const uint32_t base = smb + (ch & 1) * STAGE_BYTES;

#pragma unroll
        for (int ks = 0; ks < 4; ks++) {
            uint32_t Ah[4][4], Al[4][4], B[2][4];
#pragma unroll
            for (int mf = 0; mf < 4; mf++) {
                uint32_t offA = (uint32_t)((mw * 64 + mf * 16 + rowL) * 128 +
                                           (ks * 2 + selL) * 16);
                uint32_t a = base + (offA ^ ((offA >> 3) & 0x70));
                LDSM_X4(Ah[mf], a);
                LDSM_X4(Al[mf], a + 16384);
            }
#pragma unroll
            for (int ng = 0; ng < 2; ng++) {
                uint32_t offB = (uint32_t)((ks * 16 + rowL) * 256 +
                                           (nw * 4 + ng * 2 + selL) * 16);
                uint32_t aB = base + 32768 + (offB ^ (((offB >> 8) & 7) << 4));
                LDSM_X4T(B[ng], aB);
            }
#pragma unroll
            for (int mf = 0; mf < 4; mf++)
#pragma unroll
                for (int nf = 0; nf < 4; nf++) {
                    const int ng = nf >> 1, p = (nf & 1) * 2;
                    MMA_F16(acc[mf][nf], Ah[mf], B[ng][p], B[ng][p + 1]);
                    MMA_F16(acc[mf][nf], Al[mf], B[ng][p], B[ng][p + 1]);
                }
        }
        __syncthreads();
    }

    // ---- epilogue: out = relu(V) * ctx ----
    const int gid = L >> 2, tig = L & 3;
#pragma unroll
    for (int mf = 0; mf < 4; mf++) {
        const int r0 = mw * 64 + mf * 16 + gid;
        const float c0 = s_ctx[r0], c1 = s_ctx[r0 + 8];
        float* o0 = out + ((size_t)b * 256 + mBase + r0) * 4096 + nBase;
        float* o1 = o0 + (size_t)8 * 4096;
#pragma unroll
        for (int nf = 0; nf < 4; nf++) {
            const int col = nw * 32 + nf * 8 + tig * 2;
            float2 v0 = make_float2(fmaxf(acc[mf][nf][0], 0.f) * c0,
                                    fmaxf(acc[mf][nf][1], 0.f) * c0);
            float2 v1 = make_float2(fmaxf(acc[mf][nf][2], 0.f) * c1,
                                    fmaxf(acc[mf][nf][3], 0.f) * c1);
            *(float2*)(o0 + col) = v0;
            *(float2*)(o1 + col) = v1;
        }
    }
}

// ---------------------------------------------------------------------------
extern "C" void kernel_launch(void* const* d_in, const int* in_sizes, int n_in,
                              void* d_out, int out_size)
{
    const float* x = (const float*)d_in[0];  // (16, 256, 64, 64) f32
    const float* W = (const float*)d_in[1];  // (513, 256) f32
    float* out = (float*)d_out;              // (16, 256, 64, 64) f32

    cudaFuncSetAttribute(gemm_tc, cudaFuncAttributeMaxDynamicSharedMemorySize,
                         2 * STAGE_BYTES);

    conv_w<<<256, 256>>>(W);
    conv_xq<<<dim3(32, 16), 256>>>(x, W);
    softmax_k<<<16, 512>>>();
    y_kernel<<<dim3(256, 16), 256>>>(x);
    ctx_kernel<<<dim3(16, 32), 256>>>(W);
    gemm_tc<<<dim3(32, 2, 16), 256, 2 * STAGE_BYTES>>>(out);
}

// round 5
// speedup vs baseline: 3.4755x; 1.7208x over previous
#include <cuda_runtime.h>
#include <cuda_fp16.h>
#include <cstdint>
#include <math.h>

// ---------------- scratch (static device globals; no allocation) ----------------
__device__ float g_q[16 * 4096];
__device__ float g_s[16 * 4096];
__device__ float g_y[16 * 256];
__device__ float g_ctx[16 * 256];
// x as fp16, SAME layout as x: [b][c][n]
__device__ __half g_xh[(size_t)16 * 256 * 4096];
// W_v rows (257..512) fp16, row-major [256 m][256 k]
__device__ __half g_wh[256 * 256];

__device__ __forceinline__ uint32_t smem_u32(const void* p) {
    uint32_t a;
    asm("{ .reg .u64 t; cvta.to.shared.u64 t, %1; cvt.u32.u64 %0, t; }" : "=r"(a) : "l"(p));
    return a;
}

#define LDSM_X4(r, addr) \
    asm volatile("ldmatrix.sync.aligned.m8n8.x4.shared.b16 {%0,%1,%2,%3}, [%4];" \
        : "=r"((r)[0]), "=r"((r)[1]), "=r"((r)[2]), "=r"((r)[3]) : "r"(addr))
#define LDSM_X4T(r, addr) \
    asm volatile("ldmatrix.sync.aligned.m8n8.x4.trans.shared.b16 {%0,%1,%2,%3}, [%4];" \
        : "=r"((r)[0]), "=r"((r)[1]), "=r"((r)[2]), "=r"((r)[3]) : "r"(addr))
#define MMA_F16(d, a, b0, b1) \
    asm volatile("mma.sync.aligned.m16n8k16.row.col.f32.f16.f16.f32 " \
        "{%0,%1,%2,%3}, {%4,%5,%6,%7}, {%8,%9}, {%0,%1,%2,%3};" \
        : "+f"((d)[0]), "+f"((d)[1]), "+f"((d)[2]), "+f"((d)[3]) \
        : "r"((a)[0]), "r"((a)[1]), "r"((a)[2]), "r"((a)[3]), "r"(b0), "r"(b1))
#define CP_ASYNC16(dst, src) \
    asm volatile("cp.async.cg.shared.global [%0], [%1], 16;" :: "r"(dst), "l"(src))
#define CP_COMMIT() asm volatile("cp.async.commit_group;" ::: "memory")
#define CP_WAIT(n)  asm volatile("cp.async.wait_group %0;" :: "n"(n) : "memory")

// ---------------------------------------------------------------------------
// Kernel A: W_v (rows 257..512) -> fp16.
// ---------------------------------------------------------------------------
__global__ __launch_bounds__(256) void conv_w(const float* __restrict__ W)
{
    int r = blockIdx.x, c = threadIdx.x;
    g_wh[r * 256 + c] = __float2half_rn(W[(size_t)(257 + r) * 256 + c]);
}

// ---------------------------------------------------------------------------
// Kernel B: x -> fp16 (same layout) and q[b,n] = sum_c W[0,c]*x[b,c,n].
// Grid (32 n-tiles, 16 b), 256 threads: thread owns an n-pair, c strided by 4.
// float2 loads / half2 stores (fully coalesced both directions).
// ---------------------------------------------------------------------------
__global__ __launch_bounds__(256) void conv_xq(const float* __restrict__ x,
                                               const float* __restrict__ W)
{
    __shared__ float s_wq[256];
    __shared__ float s_red[4][128];
    const int b = blockIdx.y;
    const int nBase = blockIdx.x * 128;
    const int t = threadIdx.x;
    const int cq = t >> 6;          // 0..3  (c phase)
    const int np = t & 63;          // n-pair index
    const int n = np * 2;

    s_wq[t] = W[t];  // W row 0 = q weights
    __syncthreads();

    float qp0 = 0.f, qp1 = 0.f;
#pragma unroll 8
    for (int c = cq; c < 256; c += 4) {
        size_t idx = ((size_t)b * 256 + c) * 4096 + nBase + n;
        float2 v = *(const float2*)(x + idx);
        *(__half2*)(g_xh + idx) = __floats2half2_rn(v.x, v.y);
        float wq = s_wq[c];
        qp0 += wq * v.x;
        qp1 += wq * v.y;
    }
    s_red[cq][n]     = qp0;   // safe: unique (cq, n) per thread
    s_red[cq][n + 1] = qp1;
    __syncthreads();
    if (t < 128)
        g_q[b * 4096 + nBase + t] =
            s_red[0][t] + s_red[1][t] + s_red[2][t] + s_red[3][t];
}

// ---------------------------------------------------------------------------
// Kernel C: softmax over q (16 x 4096).
// ---------------------------------------------------------------------------
__global__ __launch_bounds__(512) void softmax_k()
{
    const int b = blockIdx.x;
    const float4* q4 = (const float4*)(g_q + b * 4096);
    float4* s4 = (float4*)(g_s + b * 4096);

    float4 v0 = q4[threadIdx.x];
    float4 v1 = q4[threadIdx.x + 512];

    float m = fmaxf(fmaxf(fmaxf(v0.x, v0.y), fmaxf(v0.z, v0.w)),
                    fmaxf(fmaxf(v1.x, v1.y), fmaxf(v1.z, v1.w)));
    __shared__ float redm[16];
    __shared__ float reds[16];
#pragma unroll
    for (int o = 16; o > 0; o >>= 1) m = fmaxf(m, __shfl_xor_sync(0xffffffffu, m, o));
    if ((threadIdx.x & 31) == 0) redm[threadIdx.x >> 5] = m;
    __syncthreads();
    float gm = redm[0];
#pragma unroll
    for (int i = 1; i < 16; i++) gm = fmaxf(gm, redm[i]);

    v0.x = __expf(v0.x - gm); v0.y = __expf(v0.y - gm);
    v0.z = __expf(v0.z - gm); v0.w = __expf(v0.w - gm);
    v1.x = __expf(v1.x - gm); v1.y = __expf(v1.y - gm);
    v1.z = __expf(v1.z - gm); v1.w = __expf(v1.w - gm);

    float sum = v0.x + v0.y + v0.z + v0.w + v1.x + v1.y + v1.z + v1.w;
#pragma unroll
    for (int o = 16; o > 0; o >>= 1) sum += __shfl_xor_sync(0xffffffffu, sum, o);
    if ((threadIdx.x & 31) == 0) reds[threadIdx.x >> 5] = sum;
    __syncthreads();
    float tot = 0.f;
#pragma unroll
    for (int i = 0; i < 16; i++) tot += reds[i];
    float inv = 1.f / tot;

    v0.x *= inv; v0.y *= inv; v0.z *= inv; v0.w *= inv;
    v1.x *= inv; v1.y *= inv; v1.z *= inv; v1.w *= inv;
    s4[threadIdx.x] = v0;
    s4[threadIdx.x + 512] = v1;
}

// ---------------------------------------------------------------------------
// Kernel D: y[b,c] = sum_n x[b,c,n] * s[b,n], reading fp16 x (half traffic).
// ---------------------------------------------------------------------------
__global__ __launch_bounds__(256) void y_kernel()
{
    const int c = blockIdx.x, b = blockIdx.y;
    const uint4* xr = (const uint4*)(g_xh + ((size_t)b * 256 + c) * 4096);
    const float4* sr = (const float4*)(g_s + b * 4096);
    float acc = 0.f;
#pragma unroll
    for (int it = 0; it < 2; it++) {
        int i = it * 256 + threadIdx.x;     // uint4 = 8 halves
        uint4 xv = xr[i];
        float4 s0 = sr[i * 2];
        float4 s1 = sr[i * 2 + 1];
        float2 a = __half22float2(*(__half2*)&xv.x);
        float2 bq = __half22float2(*(__half2*)&xv.y);
        float2 cc = __half22float2(*(__half2*)&xv.z);
        float2 d = __half22float2(*(__half2*)&xv.w);
        acc += a.x * s0.x + a.y * s0.y + bq.x * s0.z + bq.y * s0.w;
        acc += cc.x * s1.x + cc.y * s1.y + d.x * s1.z + d.y * s1.w;
    }
#pragma unroll
    for (int o = 16; o > 0; o >>= 1) acc += __shfl_xor_sync(0xffffffffu, acc, o);
    __shared__ float red[8];
    if ((threadIdx.x & 31) == 0) red[threadIdx.x >> 5] = acc;
    __syncthreads();
    if (threadIdx.x == 0) {
        float tsum = 0.f;
#pragma unroll
        for (int i = 0; i < 8; i++) tsum += red[i];
        g_y[b * 256 + c] = tsum;
    }
}

// ---------------------------------------------------------------------------
// Kernel E: ctx[b,d] = sum_c W[1+d,c] * y[b,c]. One warp per d, coalesced.
// ---------------------------------------------------------------------------
__global__ __launch_bounds__(256) void ctx_kernel(const float* __restrict__ W)
{
    const int b = blockIdx.x;
    const int w = threadIdx.x >> 5, l = threadIdx.x & 31;
    const int d = blockIdx.y * 8 + w;
    __shared__ float ys[256];
    ys[threadIdx.x] = g_y[b * 256 + threadIdx.x];
    __syncthreads();
    const float* wr = W + (size_t)(1 + d) * 256;
    float acc = 0.f;
#pragma unroll
    for (int c = l; c < 256; c += 32) acc += wr[c] * ys[c];
#pragma unroll
    for (int o = 16; o > 0; o >>= 1) acc += __shfl_xor_sync(0xffffffffu, acc, o);
    if (l == 0) g_ctx[b * 256 + d] = acc;
}

// ---------------------------------------------------------------------------
// Kernel F: mma.sync fp16 GEMM  V = Wv @ x  (M=256 x N=65536 x K=256).
// CTA tile 128(m) x 128(n). 4 K-chunks of 64, ALL prefetched via cp.async
// into 4 smem stages (32KB each, 128KB total), computed with staged waits.
// 8 warps, warp tile 64(m) x 32(n). Epilogue fuses out = relu(V)*ctx.
// Stage layout: A@0 (128r x 128B, sw128 xor-by-row&7)
//               B@16K (64r x 256B, xor col16 by row&15 -> conflict-free trans)
// ---------------------------------------------------------------------------
#define STAGE_BYTES 32768

__global__ __launch_bounds__(256, 1) void gemm_tc(float* __restrict__ out)
{
    extern __shared__ char sm[];
    __shared__ float s_ctx[128];

    const int nBase = blockIdx.x * 128;
    const int mBase = blockIdx.y * 128;
    const int b = blockIdx.z;
    const uint32_t smb = smem_u32(sm);

    const int t = threadIdx.x;
    const int w = t >> 5, L = t & 31;
    const int mw = w & 1, nw = w >> 1;

    if (t < 128) s_ctx[t] = g_ctx[b * 256 + mBase + t];

    const int ra = t >> 1, ca = t & 1;  // A: 128 rows x 2 col-groups
    const int rb = t >> 2, cb = t & 3;  // B: 64 rows x 4 col-groups

    // ---- prefetch all 4 chunks ----
#pragma unroll
    for (int ch = 0; ch < 4; ch++) {
        const int k0 = ch * 64;
        const uint32_t base = smb + ch * STAGE_BYTES;
#pragma unroll
        for (int i = 0; i < 4; i++) {
            int c16 = ca * 4 + i;
            uint32_t offA = (uint32_t)(ra * 128 + c16 * 16);
            uint32_t swA = offA ^ ((offA >> 3) & 0x70);
            CP_ASYNC16(base + swA, g_wh + (size_t)(mBase + ra) * 256 + k0 + c16 * 8);
            int c16b = cb * 4 + i;
            uint32_t offB = (uint32_t)(rb * 256 + c16b * 16);
            uint32_t swB = offB ^ (((offB >> 8) & 0xF) << 4);
            CP_ASYNC16(base + 16384 + swB,
                       g_xh + ((size_t)b * 256 + k0 + rb) * 4096 + nBase + c16b * 8);
        }
        CP_COMMIT();
    }

    float acc[4][4][4];
#pragma unroll
    for (int i = 0; i < 4; i++)
#pragma unroll
        for (int j = 0; j < 4; j++)
#pragma unroll
            for (int k = 0; k < 4; k++) acc[i][j][k] = 0.f;

    const int rowL = L & 15;
    const int selL = L >> 4;

#define DO_CHUNK(CH, WAITN)                                                     \
    {                                                                           \
        CP_WAIT(WAITN);                                                         \
        __syncthreads();                                                        \
        const uint32_t base = smb + (CH) * STAGE_BYTES;                         \
        _Pragma("unroll")                                                       \
        for (int ks = 0; ks < 4; ks++) {                                        \
            uint32_t Ah[4][4], B[2][4];                                         \
            _Pragma("unroll")                                                   \
            for (int mf = 0; mf < 4; mf++) {                                    \
                uint32_t offA = (uint32_t)((mw * 64 + mf * 16 + rowL) * 128 +   \
                                           (ks * 2 + selL) * 16);               \
                LDSM_X4(Ah[mf], base + (offA ^ ((offA >> 3) & 0x70)));          \
            }                                                                   \
            _Pragma("unroll")                                                   \
            for (int ng = 0; ng < 2; ng++) {                                    \
                uint32_t offB = (uint32_t)((ks * 16 + rowL) * 256 +             \
                                           (nw * 4 + ng * 2 + selL) * 16);      \
                LDSM_X4T(B[ng], base + 16384 +                                  \
                                (offB ^ (((offB >> 8) & 0xF) << 4)));           \
            }                                                                   \
            _Pragma("unroll")                                                   \
            for (int mf = 0; mf < 4; mf++)                                      \
                _Pragma("unroll")                                               \
                for (int nf = 0; nf < 4; nf++) {                                \
                    const int ng = nf >> 1, p = (nf & 1) * 2;                   \
                    MMA_F16(acc[mf][nf], Ah[mf], B[ng][p], B[ng][p + 1]);       \
                }                                                               \
        }                                                                       \
    }

    DO_CHUNK(0, 3)
    DO_CHUNK(1, 2)
    DO_CHUNK(2, 1)
    DO_CHUNK(3, 0)
#undef DO_CHUNK

    // ---- epilogue: out = relu(V) * ctx ----
    const int gid = L >> 2, tig = L & 3;
#pragma unroll
    for (int mf = 0; mf < 4; mf++) {
        const int r0 = mw * 64 + mf * 16 + gid;
        const float c0 = s_ctx[r0], c1 = s_ctx[r0 + 8];
        float* o0 = out + ((size_t)b * 256 + mBase + r0) * 4096 + nBase;
        float* o1 = o0 + (size_t)8 * 4096;
#pragma unroll
        for (int nf = 0; nf < 4; nf++) {
            const int col = nw * 32 + nf * 8 + tig * 2;
            float2 v0 = make_float2(fmaxf(acc[mf][nf][0], 0.f) * c0,
                                    fmaxf(acc[mf][nf][1], 0.f) * c0);
            float2 v1 = make_float2(fmaxf(acc[mf][nf][2], 0.f) * c1,
                                    fmaxf(acc[mf][nf][3], 0.f) * c1);
            *(float2*)(o0 + col) = v0;
            *(float2*)(o1 + col) = v1;
        }
    }
}

// ---------------------------------------------------------------------------
extern "C" void kernel_launch(void* const* d_in, const int* in_sizes, int n_in,
                              void* d_out, int out_size)
{
    const float* x = (const float*)d_in[0];  // (16, 256, 64, 64) f32
    const float* W = (const float*)d_in[1];  // (513, 256) f32
    float* out = (float*)d_out;              // (16, 256, 64, 64) f32

    cudaFuncSetAttribute(gemm_tc, cudaFuncAttributeMaxDynamicSharedMemorySize,
                         4 * STAGE_BYTES);

    conv_w<<<256, 256>>>(W);
    conv_xq<<<dim3(32, 16), 256>>>(x, W);
    softmax_k<<<16, 512>>>();
    y_kernel<<<dim3(256, 16), 256>>>();
    ctx_kernel<<<dim3(16, 32), 256>>>(W);
    gemm_tc<<<dim3(32, 2, 16), 256, 4 * STAGE_BYTES>>>(out);
}

// round 6
// speedup vs baseline: 3.5126x; 1.0107x over previous
#include <cuda_runtime.h>
#include <cuda_fp16.h>
#include <cstdint>
#include <math.h>

// ---------------- scratch (static device globals; no allocation) ----------------
__device__ float g_q[16 * 4096];
__device__ float g_s[16 * 4096];
__device__ float g_y[16 * 256];
__device__ float g_ctx[16 * 256];
// x as fp16, SAME layout as x: [b][c][n]
__device__ __half g_xh[(size_t)16 * 256 * 4096];
// W_v rows (257..512) fp16, row-major [256 m][256 k]
__device__ __half g_wh[256 * 256];

__device__ __forceinline__ uint32_t smem_u32(const void* p) {
    uint32_t a;
    asm("{ .reg .u64 t; cvta.to.shared.u64 t, %1; cvt.u32.u64 %0, t; }" : "=r"(a) : "l"(p));
    return a;
}

#define LDSM_X4(r, addr) \
    asm volatile("ldmatrix.sync.aligned.m8n8.x4.shared.b16 {%0,%1,%2,%3}, [%4];" \
        : "=r"((r)[0]), "=r"((r)[1]), "=r"((r)[2]), "=r"((r)[3]) : "r"(addr))
#define LDSM_X4T(r, addr) \
    asm volatile("ldmatrix.sync.aligned.m8n8.x4.trans.shared.b16 {%0,%1,%2,%3}, [%4];" \
        : "=r"((r)[0]), "=r"((r)[1]), "=r"((r)[2]), "=r"((r)[3]) : "r"(addr))
#define MMA_F16(d, a, b0, b1) \
    asm volatile("mma.sync.aligned.m16n8k16.row.col.f32.f16.f16.f32 " \
        "{%0,%1,%2,%3}, {%4,%5,%6,%7}, {%8,%9}, {%0,%1,%2,%3};" \
        : "+f"((d)[0]), "+f"((d)[1]), "+f"((d)[2]), "+f"((d)[3]) \
        : "r"((a)[0]), "r"((a)[1]), "r"((a)[2]), "r"((a)[3]), "r"(b0), "r"(b1))
#define CP_ASYNC16(dst, src) \
    asm volatile("cp.async.cg.shared.global [%0], [%1], 16;" :: "r"(dst), "l"(src))
#define CP_COMMIT() asm volatile("cp.async.commit_group;" ::: "memory")
#define CP_WAIT(n)  asm volatile("cp.async.wait_group %0;" :: "n"(n) : "memory")

// ---------------------------------------------------------------------------
// Kernel A: W_v (rows 257..512) -> fp16.
// ---------------------------------------------------------------------------
__global__ __launch_bounds__(256) void conv_w(const float* __restrict__ W)
{
    int r = blockIdx.x, c = threadIdx.x;
    g_wh[r * 256 + c] = __float2half_rn(W[(size_t)(257 + r) * 256 + c]);
}

// ---------------------------------------------------------------------------
// Kernel B: x -> fp16 (same layout) and q[b,n] = sum_c W[0,c]*x[b,c,n].
// Grid (16 n-tiles of 256, 16 b), 256 threads: thread owns 4 n (float4 load,
// 8B packed half store), c strided by 4 phases.
// ---------------------------------------------------------------------------
__global__ __launch_bounds__(256) void conv_xq(const float* __restrict__ x,
                                               const float* __restrict__ W)
{
    __shared__ float s_wq[256];
    __shared__ float s_red[4][256];
    const int b = blockIdx.y;
    const int nBase = blockIdx.x * 256;
    const int t = threadIdx.x;
    const int cq = t >> 6;          // 0..3 (c phase)
    const int n = (t & 63) * 4;     // n offset within tile

    s_wq[t] = W[t];  // W row 0 = q weights
    __syncthreads();

    float qp0 = 0.f, qp1 = 0.f, qp2 = 0.f, qp3 = 0.f;
#pragma unroll 8
    for (int c = cq; c < 256; c += 4) {
        size_t idx = ((size_t)b * 256 + c) * 4096 + nBase + n;
        float4 v = *(const float4*)(x + idx);
        __half2 h01 = __floats2half2_rn(v.x, v.y);
        __half2 h23 = __floats2half2_rn(v.z, v.w);
        uint2 pk;
        pk.x = *(uint32_t*)&h01;
        pk.y = *(uint32_t*)&h23;
        *(uint2*)(g_xh + idx) = pk;
        float wq = s_wq[c];
        qp0 += wq * v.x; qp1 += wq * v.y; qp2 += wq * v.z; qp3 += wq * v.w;
    }
    *(float4*)&s_red[cq][n] = make_float4(qp0, qp1, qp2, qp3);
    __syncthreads();
    g_q[b * 4096 + nBase + t] =
        s_red[0][t] + s_red[1][t] + s_red[2][t] + s_red[3][t];
}

// ---------------------------------------------------------------------------
// Kernel C: softmax over q (16 x 4096).
// ---------------------------------------------------------------------------
__global__ __launch_bounds__(512) void softmax_k()
{
    const int b = blockIdx.x;
    const float4* q4 = (const float4*)(g_q + b * 4096);
    float4* s4 = (float4*)(g_s + b * 4096);

    float4 v0 = q4[threadIdx.x];
    float4 v1 = q4[threadIdx.x + 512];

    float m = fmaxf(fmaxf(fmaxf(v0.x, v0.y), fmaxf(v0.z, v0.w)),
                    fmaxf(fmaxf(v1.x, v1.y), fmaxf(v1.z, v1.w)));
    __shared__ float redm[16];
    __shared__ float reds[16];
#pragma unroll
    for (int o = 16; o > 0; o >>= 1) m = fmaxf(m, __shfl_xor_sync(0xffffffffu, m, o));
    if ((threadIdx.x & 31) == 0) redm[threadIdx.x >> 5] = m;
    __syncthreads();
    float gm = redm[0];
#pragma unroll
    for (int i = 1; i < 16; i++) gm = fmaxf(gm, redm[i]);

    v0.x = __expf(v0.x - gm); v0.y = __expf(v0.y - gm);
    v0.z = __expf(v0.z - gm); v0.w = __expf(v0.w - gm);
    v1.x = __expf(v1.x - gm); v1.y = __expf(v1.y - gm);
    v1.z = __expf(v1.z - gm); v1.w = __expf(v1.w - gm);

    float sum = v0.x + v0.y + v0.z + v0.w + v1.x + v1.y + v1.z + v1.w;
#pragma unroll
    for (int o = 16; o > 0; o >>= 1) sum += __shfl_xor_sync(0xffffffffu, sum, o);
    if ((threadIdx.x & 31) == 0) reds[threadIdx.x >> 5] = sum;
    __syncthreads();
    float tot = 0.f;
#pragma unroll
    for (int i = 0; i < 16; i++) tot += reds[i];
    float inv = 1.f / tot;

    v0.x *= inv; v0.y *= inv; v0.z *= inv; v0.w *= inv;
    v1.x *= inv; v1.y *= inv; v1.z *= inv; v1.w *= inv;
    s4[threadIdx.x] = v0;
    s4[threadIdx.x + 512] = v1;
}

// ---------------------------------------------------------------------------
// Kernel D: y[b,c] = sum_n x[b,c,n] * s[b,n].
// Block = (8 c-rows, b): s[b] staged once in smem, one warp per c-row,
// 16 independent uint4 loads per lane (high MLP), warp-reduce only.
// ---------------------------------------------------------------------------
__global__ __launch_bounds__(256) void y_kernel()
{
    __shared__ float s_s[4096];
    const int b = blockIdx.y;
    const int t = threadIdx.x;
    const int w = t >> 5, L = t & 31;

    for (int i = t; i < 1024; i += 256)
        *(float4*)&s_s[i * 4] = ((const float4*)(g_s + b * 4096))[i];
    __syncthreads();

    const int c = blockIdx.x * 8 + w;
    const uint4* xr = (const uint4*)(g_xh + ((size_t)b * 256 + c) * 4096);
    float acc = 0.f;
#pragma unroll
    for (int k = 0; k < 16; k++) {
        int i = k * 32 + L;
        uint4 xv = xr[i];
        const float4* sp = (const float4*)&s_s[i * 8];
        float4 s0 = sp[0], s1 = sp[1];
        float2 a = __half22float2(*(__half2*)&xv.x);
        float2 bb = __half22float2(*(__half2*)&xv.y);
        float2 cc = __half22float2(*(__half2*)&xv.z);
        float2 d = __half22float2(*(__half2*)&xv.w);
        acc += a.x * s0.x + a.y * s0.y + bb.x * s0.z + bb.y * s0.w;
        acc += cc.x * s1.x + cc.y * s1.y + d.x * s1.z + d.y * s1.w;
    }
#pragma unroll
    for (int o = 16; o > 0; o >>= 1) acc += __shfl_xor_sync(0xffffffffu, acc, o);
    if (L == 0) g_y[b * 256 + c] = acc;
}

// ---------------------------------------------------------------------------
// Kernel E: ctx[b,d] = sum_c W[1+d,c] * y[b,c]. One warp per d, coalesced.
// ---------------------------------------------------------------------------
__global__ __launch_bounds__(256) void ctx_kernel(const float* __restrict__ W)
{
    const int b = blockIdx.x;
    const int w = threadIdx.x >> 5, l = threadIdx.x & 31;
    const int d = blockIdx.y * 8 + w;
    __shared__ float ys[256];
    ys[threadIdx.x] = g_y[b * 256 + threadIdx.x];
    __syncthreads();
    const float* wr = W + (size_t)(1 + d) * 256;
    float acc = 0.f;
#pragma unroll
    for (int c = l; c < 256; c += 32) acc += wr[c] * ys[c];
#pragma unroll
    for (int o = 16; o > 0; o >>= 1) acc += __shfl_xor_sync(0xffffffffu, acc, o);
    if (l == 0) g_ctx[b * 256 + d] = acc;
}

// ---------------------------------------------------------------------------
// Kernel F: mma.sync fp16 GEMM  V = Wv @ x  (M=256 x N=65536 x K=256).
// CTA tile 256(m) x 128(n) — x read EXACTLY ONCE. 512 threads, 16 warps,
// warp tile 64x32 (4x4 warp grid). 4 K-chunks of 64, all prefetched via
// cp.async into 4 smem stages (48KB each, 192KB total).
// Stage layout: A@0  (256r x 128B, sw128 xor)
//               B@32K (64r x 256B, xor col16 by row&15 -> conflict-free trans)
// Epilogue fuses out = relu(V) * ctx[b,m].
// ---------------------------------------------------------------------------
#define STAGE_BYTES 49152

__global__ __launch_bounds__(512, 1) void gemm_tc(float* __restrict__ out)
{
    extern __shared__ char sm[];
    __shared__ float s_ctx[256];

    const int nBase = blockIdx.x * 128;
    const int b = blockIdx.y;
    const uint32_t smb = smem_u32(sm);

    const int t = threadIdx.x;
    const int w = t >> 5, L = t & 31;
    const int mw = w & 3, nw = w >> 2;   // 4 m-warps x 4 n-warps

    if (t < 256) s_ctx[t] = g_ctx[b * 256 + t];

    // ---- prefetch all 4 K-chunks ----
#pragma unroll
    for (int ch = 0; ch < 4; ch++) {
        const int k0 = ch * 64;
        const uint32_t base = smb + ch * STAGE_BYTES;
#pragma unroll
        for (int i = 0; i < 4; i++) {          // A: 2048 16B-chunks / 512 thr
            int u = i * 512 + t;
            int ra = u >> 3, ca = u & 7;
            uint32_t offA = (uint32_t)(ra * 128 + ca * 16);
            uint32_t swA = offA ^ ((offA >> 3) & 0x70);
            CP_ASYNC16(base + swA, g_wh + (size_t)ra * 256 + k0 + ca * 8);
        }
#pragma unroll
        for (int i = 0; i < 2; i++) {          // B: 1024 16B-chunks / 512 thr
            int u = i * 512 + t;
            int rb = u >> 4, cb = u & 15;
            uint32_t offB = (uint32_t)(rb * 256 + cb * 16);
            uint32_t swB = offB ^ (((offB >> 8) & 0xF) << 4);
            CP_ASYNC16(base + 32768 + swB,
                       g_xh + ((size_t)b * 256 + k0 + rb) * 4096 + nBase + cb * 8);
        }
        CP_COMMIT();
    }

    float acc[4][4][4];
#pragma unroll
    for (int i = 0; i < 4; i++)
#pragma unroll
        for (int j = 0; j < 4; j++)
#pragma unroll
            for (int k = 0; k < 4; k++) acc[i][j][k] = 0.f;

    const int rowL = L & 15;
    const int selL = L >> 4;

#define DO_CHUNK(CH, WAITN)                                                     \
    {                                                                           \
        CP_WAIT(WAITN);                                                         \
        __syncthreads();                                                        \
        const uint32_t base = smb + (CH) * STAGE_BYTES;                         \
        _Pragma("unroll")                                                       \
        for (int ks = 0; ks < 4; ks++) {                                        \
            uint32_t Ah[4][4], B[2][4];                                         \
            _Pragma("unroll")                                                   \
            for (int mf = 0; mf < 4; mf++) {                                    \
                uint32_t offA = (uint32_t)((mw * 64 + mf * 16 + rowL) * 128 +   \
                                           (ks * 2 + selL) * 16);               \
                LDSM_X4(Ah[mf], base + (offA ^ ((offA >> 3) & 0x70)));          \
            }                                                                   \
            _Pragma("unroll")                                                   \
            for (int ng = 0; ng < 2; ng++) {                                    \
                uint32_t offB = (uint32_t)((ks * 16 + rowL) * 256 +             \
                                           (nw * 4 + ng * 2 + selL) * 16);      \
                LDSM_X4T(B[ng], base + 32768 +                                  \
                                (offB ^ (((offB >> 8) & 0xF) << 4)));           \
            }                                                                   \
            _Pragma("unroll")                                                   \
            for (int mf = 0; mf < 4; mf++)                                      \
                _Pragma("unroll")                                               \
                for (int nf = 0; nf < 4; nf++) {                                \
                    const int ng = nf >> 1, p = (nf & 1) * 2;                   \
                    MMA_F16(acc[mf][nf], Ah[mf], B[ng][p], B[ng][p + 1]);       \
                }                                                               \
        }                                                                       \
    }

    DO_CHUNK(0, 3)
    DO_CHUNK(1, 2)
    DO_CHUNK(2, 1)
    DO_CHUNK(3, 0)
#undef DO_CHUNK

    // ---- epilogue: out = relu(V) * ctx ----
    const int gid = L >> 2, tig = L & 3;
#pragma unroll
    for (int mf = 0; mf < 4; mf++) {
        const int r0 = mw * 64 + mf * 16 + gid;
        const float c0 = s_ctx[r0], c1 = s_ctx[r0 + 8];
        float* o0 = out + ((size_t)b * 256 + r0) * 4096 + nBase;
        float* o1 = o0 + (size_t)8 * 4096;
#pragma unroll
        for (int nf = 0; nf < 4; nf++) {
            const int col = nw * 32 + nf * 8 + tig * 2;
            float2 v0 = make_float2(fmaxf(acc[mf][nf][0], 0.f) * c0,
                                    fmaxf(acc[mf][nf][1], 0.f) * c0);
            float2 v1 = make_float2(fmaxf(acc[mf][nf][2], 0.f) * c1,
                                    fmaxf(acc[mf][nf][3], 0.f) * c1);
            *(float2*)(o0 + col) = v0;
            *(float2*)(o1 + col) = v1;
        }
    }
}

// ---------------------------------------------------------------------------
extern "C" void kernel_launch(void* const* d_in, const int* in_sizes, int n_in,
                              void* d_out, int out_size)
{
    const float* x = (const float*)d_in[0];  // (16, 256, 64, 64) f32
    const float* W = (const float*)d_in[1];  // (513, 256) f32
    float* out = (float*)d_out;              // (16, 256, 64, 64) f32

    cudaFuncSetAttribute(gemm_tc, cudaFuncAttributeMaxDynamicSharedMemorySize,
                         4 * STAGE_BYTES);

    conv_w<<<256, 256>>>(W);
    conv_xq<<<dim3(16, 16), 256>>>(x, W);
    softmax_k<<<16, 512>>>();
    y_kernel<<<dim3(32, 16), 256>>>();
    ctx_kernel<<<dim3(16, 32), 256>>>(W);
    gemm_tc<<<dim3(32, 16), 512, 4 * STAGE_BYTES>>>(out);
}